// round 13
// baseline (speedup 1.0000x reference)
#include <cuda_runtime.h>
#include <cuda/atomic>
#include <math.h>

#define NB     4
#define NPTS   8192
#define NPOINT 409          /* int(8192*0.05) */
#define NG     (NB*NPOINT)  /* 1636 */
#define CAP    256
#define SEG    64
#define NBKT   2048         /* counting-sort buckets (11-bit Morton prefix) */

// ---------------- device scratch (no allocations allowed) ----------------
__device__ double g_acc[2];                   // [0]=uniform, [1]=repulsion sum
__device__ float  g_newxyz[NB*NPOINT*3];      // FPS centers
__device__ float4 g_sorted[NB*NPTS];          // Morton-bucketed points (w = orig idx)
__device__ float4 g_pcd4[NB*NPTS];            // original-order points, float4
__device__ int    g_progress[NB];             // fps centers published per batch

// exact-rounding distance (FPS argmax must match reference exactly)
__device__ __forceinline__ float sqdist_rn(float ax, float ay, float az,
                                           float bx, float by, float bz) {
    float dx = __fadd_rn(ax, -bx);
    float dy = __fadd_rn(ay, -by);
    float dz = __fadd_rn(az, -bz);
    return __fadd_rn(__fadd_rn(__fmul_rn(dx, dx), __fmul_rn(dy, dy)),
                     __fmul_rn(dz, dz));
}
// fast distance (FMA) — continuous-use sites only
__device__ __forceinline__ float sqdist_f(float ax, float ay, float az,
                                          float bx, float by, float bz) {
    float dx = ax - bx, dy = ay - by, dz = az - bz;
    return fmaf(dx, dx, fmaf(dy, dy, dz * dz));
}

__device__ __forceinline__ float warp_sum(float v) {
    #pragma unroll
    for (int o = 16; o > 0; o >>= 1) v += __shfl_down_sync(0xffffffffu, v, o);
    return v;
}

// ============  Morton counting sort (2048 buckets): one block/batch  ============
__device__ __forceinline__ unsigned expandb(unsigned v) {
    v &= 1023u;
    v = (v | (v << 16)) & 0x030000FFu;
    v = (v | (v << 8))  & 0x0300F00Fu;
    v = (v | (v << 4))  & 0x030C30C3u;
    v = (v | (v << 2))  & 0x09249249u;
    return v;
}

__global__ void __launch_bounds__(1024, 1)
sort_kernel(const float* __restrict__ pcd) {
    __shared__ unsigned codes[NPTS];              // 32 KB: (bucket<<13)|orig_idx
    __shared__ int hist[NBKT];                    // 8 KB
    __shared__ int wsum[32];
    const int b    = blockIdx.x;
    const int tid  = threadIdx.x;
    const int lane = tid & 31;
    const int w    = tid >> 5;
    const float* P = pcd + b * NPTS * 3;

    if (tid == 0) {
        g_progress[b] = 0;                        // reset pipeline counter
        if (b == 0) { g_acc[0] = 0.0; g_acc[1] = 0.0; }
    }

    for (int i = tid; i < NBKT; i += 1024) hist[i] = 0;
    __syncthreads();

    for (int j = tid; j < NPTS; j += 1024) {
        float x = P[3*j], y = P[3*j+1], z = P[3*j+2];
        g_pcd4[b*NPTS + j] = make_float4(x, y, z, 0.0f);
        unsigned ux = (unsigned)fminf(fmaxf((x + 1.0f) * 32.0f, 0.0f), 63.0f);
        unsigned uy = (unsigned)fminf(fmaxf((y + 1.0f) * 32.0f, 0.0f), 63.0f);
        unsigned uz = (unsigned)fminf(fmaxf((z + 1.0f) * 32.0f, 0.0f), 63.0f);
        unsigned m = expandb(ux) | (expandb(uy) << 1) | (expandb(uz) << 2); // 18 bits
        unsigned bkt = m >> 7;                    // 11-bit bucket
        codes[j] = (bkt << 13) | (unsigned)j;
        atomicAdd(&hist[bkt], 1);
    }
    __syncthreads();

    // exclusive prefix over 2048 buckets (2 per thread)
    int base = tid * 2;
    int s0 = hist[base], s1 = hist[base+1];
    int tsum = s0 + s1;
    int scan = tsum;
    #pragma unroll
    for (int o = 1; o < 32; o <<= 1) {
        int v = __shfl_up_sync(0xffffffffu, scan, o);
        if (lane >= o) scan += v;
    }
    if (lane == 31) wsum[w] = scan;
    __syncthreads();
    if (w == 0) {
        int v = wsum[lane], s = v;
        #pragma unroll
        for (int o = 1; o < 32; o <<= 1) {
            int t = __shfl_up_sync(0xffffffffu, s, o);
            if (lane >= o) s += t;
        }
        wsum[lane] = s - v;                       // exclusive warp offsets
    }
    __syncthreads();
    int excl = wsum[w] + (scan - tsum);
    hist[base]   = excl;
    hist[base+1] = excl + s0;
    __syncthreads();

    // scatter (order within bucket arbitrary — only grouping matters)
    for (int j = tid; j < NPTS; j += 1024) {
        unsigned c = codes[j];
        int bkt = (int)(c >> 13);
        int src = (int)(c & 0x1FFFu);
        int pos = atomicAdd(&hist[bkt], 1);
        float4 f = g_pcd4[b*NPTS + src];
        f.w = __int_as_float(src);
        g_sorted[b*NPTS + pos] = f;
    }
}

// ======  FPS: 512 thr, 2×8-pt AABB groups/lane, cached warp keys, redux  ======
__global__ void __launch_bounds__(512, 1)
fps_kernel(const float* __restrict__ pcd) {
    extern __shared__ float4 ctab[];              // [NPTS] orig-index coords, 128 KB

    const int b    = blockIdx.x;
    const int tid  = threadIdx.x;
    const int w    = tid >> 5;                    // 0..15
    const int lane = tid & 31;
    const float4* S  = g_sorted + b * NPTS;
    const float4* P4 = g_pcd4  + b * NPTS;
    const float*  P  = pcd + b * NPTS * 3;

    for (int j = tid; j < NPTS; j += 512)
        ctab[j] = P4[j];

    // lane owns 16 CONTIGUOUS bucketed points [tid*16, tid*16+16) as 2 groups of 8
    float xs[16], ys[16], zs[16], dist[16];
    unsigned loid[16];                            // 8191 - orig_idx
    #pragma unroll
    for (int k = 0; k < 16; k++) {
        float4 f = S[tid*16 + k];
        xs[k] = f.x; ys[k] = f.y; zs[k] = f.z;
        dist[k] = 1e10f;
        loid[k] = 8191u - (unsigned)__float_as_int(f.w);
    }

    // per-group AABBs
    float lox0=xs[0],hix0=xs[0],loy0=ys[0],hiy0=ys[0],loz0=zs[0],hiz0=zs[0];
    float lox1=xs[8],hix1=xs[8],loy1=ys[8],hiy1=ys[8],loz1=zs[8],hiz1=zs[8];
    #pragma unroll
    for (int k = 1; k < 8; k++) {
        lox0=fminf(lox0,xs[k]);   hix0=fmaxf(hix0,xs[k]);
        loy0=fminf(loy0,ys[k]);   hiy0=fmaxf(hiy0,ys[k]);
        loz0=fminf(loz0,zs[k]);   hiz0=fmaxf(hiz0,zs[k]);
        lox1=fminf(lox1,xs[8+k]); hix1=fmaxf(hix1,xs[8+k]);
        loy1=fminf(loy1,ys[8+k]); hiy1=fmaxf(hiy1,ys[8+k]);
        loz1=fminf(loz1,zs[8+k]); hiz1=fmaxf(hiz1,zs[8+k]);
    }

    // per-group cached keys (max dist | tie-break) and lane key
    unsigned long long gkey0, gkey1, lkey;
    {
        unsigned b0 = 0, b1 = 0;
        #pragma unroll
        for (int k = 0; k < 8; k++) {
            b0 = loid[k]   > b0 ? loid[k]   : b0;
            b1 = loid[8+k] > b1 ? loid[8+k] : b1;
        }
        unsigned long long hi = (unsigned long long)__float_as_uint(1e10f) << 32;
        gkey0 = hi | b0; gkey1 = hi | b1;
        lkey  = gkey0 > gkey1 ? gkey0 : gkey1;
    }
    float dmax0 = 1e10f, dmax1 = 1e10f;

    __shared__ unsigned long long skey[32];
    if (tid < 32) skey[tid] = 0ull;               // lanes 16..31 stay 0 (never win)

    float fx = P[0], fy = P[1], fz = P[2];        // far_0 = original index 0
    if (tid == 0) {
        g_newxyz[b*NPOINT*3 + 0] = fx;
        g_newxyz[b*NPOINT*3 + 1] = fy;
        g_newxyz[b*NPOINT*3 + 2] = fz;
        cuda::atomic_ref<int, cuda::thread_scope_device> pr(g_progress[b]);
        pr.store(1, cuda::memory_order_release);
    }
    __syncthreads();

    for (int s = 1; s < NPOINT; s++) {
        // per-group lower bounds (deflated for fp safety)
        float ax0 = fmaxf(fmaxf(lox0 - fx, fx - hix0), 0.0f);
        float ay0 = fmaxf(fmaxf(loy0 - fy, fy - hiy0), 0.0f);
        float az0 = fmaxf(fmaxf(loz0 - fz, fz - hiz0), 0.0f);
        bool a0 = (ax0*ax0 + ay0*ay0 + az0*az0) * 0.999f < dmax0;
        float ax1 = fmaxf(fmaxf(lox1 - fx, fx - hix1), 0.0f);
        float ay1 = fmaxf(fmaxf(loy1 - fy, fy - hiy1), 0.0f);
        float az1 = fmaxf(fmaxf(loz1 - fz, fz - hiz1), 0.0f);
        bool a1 = (ax1*ax1 + ay1*ay1 + az1*az1) * 0.999f < dmax1;

        if (__ballot_sync(0xffffffffu, a0 | a1)) {
            if (a0) {
                unsigned long long kmax = 0ull;
                #pragma unroll
                for (int k = 0; k < 8; k++) {
                    float d  = sqdist_rn(xs[k], ys[k], zs[k], fx, fy, fz);
                    float nd = fminf(dist[k], d);
                    dist[k]  = nd;
                    unsigned long long kk =
                        ((unsigned long long)__float_as_uint(nd) << 32) | loid[k];
                    kmax = kk > kmax ? kk : kmax;
                }
                gkey0 = kmax;
                dmax0 = __uint_as_float((unsigned)(kmax >> 32));
            }
            if (a1) {
                unsigned long long kmax = 0ull;
                #pragma unroll
                for (int k = 0; k < 8; k++) {
                    float d  = sqdist_rn(xs[8+k], ys[8+k], zs[8+k], fx, fy, fz);
                    float nd = fminf(dist[8+k], d);
                    dist[8+k] = nd;
                    unsigned long long kk =
                        ((unsigned long long)__float_as_uint(nd) << 32) | loid[8+k];
                    kmax = kk > kmax ? kk : kmax;
                }
                gkey1 = kmax;
                dmax1 = __uint_as_float((unsigned)(kmax >> 32));
            }
            if (a0 | a1) lkey = gkey0 > gkey1 ? gkey0 : gkey1;
            // warp argmax (only when warp has an active lane; else skey stale-valid)
            unsigned vb = (unsigned)(lkey >> 32);
            unsigned m  = __reduce_max_sync(0xffffffffu, vb);
            unsigned lo = (vb == m) ? (unsigned)lkey : 0u;
            unsigned l  = __reduce_max_sync(0xffffffffu, lo);
            if (lane == 0)
                skey[w] = ((unsigned long long)m << 32) | l;
        }
        __syncthreads();
        // every warp redundantly reduces the 16 warp keys (no 2nd barrier)
        unsigned long long k = skey[lane];
        unsigned hi2 = (unsigned)(k >> 32);
        unsigned m2  = __reduce_max_sync(0xffffffffu, hi2);
        unsigned lo2 = (hi2 == m2) ? (unsigned)k : 0u;
        unsigned l2  = __reduce_max_sync(0xffffffffu, lo2);
        int oi = 8191 - (int)l2;
        float4 c = ctab[oi];                      // same addr warp-wide: broadcast
        fx = c.x; fy = c.y; fz = c.z;
        if (tid == 0) {
            g_newxyz[(b*NPOINT + s)*3 + 0] = fx;
            g_newxyz[(b*NPOINT + s)*3 + 1] = fy;
            g_newxyz[(b*NPOINT + s)*3 + 2] = fz;
            cuda::atomic_ref<int, cuda::thread_scope_device> pr(g_progress[b]);
            pr.store(s + 1, cuda::memory_order_release);
        }
    }
}

// =====================  Repulsion: one thread per query point  =====================
#define RTILE 256

#define INSERT5(dv) do {                                   \
    float _d = (dv);                                       \
    if (_d < s4) { s4 = _d;                                \
        if (s4 < s3) { float _t = s3; s3 = s4; s4 = _t; }  \
        if (s3 < s2) { float _t = s2; s2 = s3; s3 = _t; }  \
        if (s2 < s1) { float _t = s1; s1 = s2; s2 = _t; }  \
        if (s1 < s0) { float _t = s0; s0 = s1; s1 = _t; }  \
    } } while (0)

__global__ void __launch_bounds__(RTILE)
repulsion_kernel(const float* __restrict__ pcd, float r2, float radius, float hh) {
    const int blocks_per_b = NPTS / RTILE;
    const int b  = blockIdx.x / blocks_per_b;
    const int qi = (blockIdx.x % blocks_per_b) * RTILE + threadIdx.x;
    const float* P = pcd + b * NPTS * 3;

    const float qx = P[3*qi], qy = P[3*qi+1], qz = P[3*qi+2];

    __shared__ float4 sp[RTILE];

    float s0 = 1e30f, s1 = 1e30f, s2 = 1e30f, s3 = 1e30f, s4 = 1e30f;
    int   c  = 0;
    float h0 = 0.0f;

    for (int t = 0; t < NPTS; t += RTILE) {
        int j = t + threadIdx.x;
        sp[threadIdx.x] = make_float4(P[3*j], P[3*j+1], P[3*j+2], 0.0f);
        __syncthreads();
        #pragma unroll 8
        for (int u = 0; u < RTILE; u++) {
            float4 p = sp[u];
            float d = sqdist_f(p.x, p.y, p.z, qx, qy, qz);
            if (d <= r2 && c < 20) {
                if (c == 0) h0 = d;
                c++;
                INSERT5(d);
            }
        }
        __syncthreads();
    }

    int pads = 20 - c;
    if (pads > 5) pads = 5;
    for (int k = 0; k < pads; k++) INSERT5(h0);

    float acc = 0.0f;
    acc += radius - sqrtf(s1) * expf(-(s1 / hh));
    acc += radius - sqrtf(s2) * expf(-(s2 / hh));
    acc += radius - sqrtf(s3) * expf(-(s3 / hh));
    acc += radius - sqrtf(s4) * expf(-(s4 / hh));

    float ws = warp_sum(acc);
    __shared__ float red[RTILE/32];
    if ((threadIdx.x & 31) == 0) red[threadIdx.x >> 5] = ws;
    __syncthreads();
    if (threadIdx.x == 0) {
        float tot = 0.0f;
        #pragma unroll
        for (int w = 0; w < RTILE/32; w++) tot += red[w];
        atomicAdd(&g_acc[1], (double)tot);
    }
}

// ==========  Uniform loss: one BLOCK per center, pipelined behind fps  ==========
struct ULevels {
    float  r2[5];
    float  el[5];
    float  den[5];
    double w[5];
    int    ns[5];
};

__device__ float eval_level(const float4* H, int n_stored, int true_cnt,
                            float r2, float el, float den, int ns, int lane)
{
    int u = true_cnt < ns ? true_cnt : ns;
    float lsum = 0.0f;
    int jstart = 0;
    if (u < ns) {
        if (lane == 0) {
            float ud = sqrtf(1e-8f);
            float t  = ud - el;
            lsum += (float)(ns - u + 1) * ((t * t) / den);
        }
        jstart = 1;
    }
    for (int j = jstart + lane; j < u; j += 32) {
        float xj = 0.f, yj = 0.f, zj = 0.f;
        int seen = 0;
        for (int i = 0; i < n_stored; i++) {
            float4 h = H[i];
            if (h.w <= r2) {
                if (seen == j) { xj = h.x; yj = h.y; zj = h.z; break; }
                seen++;
            }
        }
        float m1 = 1e30f;
        seen = 0;
        for (int i = 0; i < n_stored && seen < u; i++) {
            float4 h = H[i];
            if (h.w <= r2) {
                if (seen != j) {
                    float d = sqdist_f(h.x, h.y, h.z, xj, yj, zj);
                    m1 = fminf(m1, d);
                }
                seen++;
            }
        }
        float ud = sqrtf(fabsf(m1 + 1e-8f));
        float t  = ud - el;
        lsum += (t * t) / den;
    }
    return lsum;
}

// warp-parallel count of hits at radius r2 among H[0..tot)
__device__ __forceinline__ int count_hits(const float4* H, int tot, float r2, int lane) {
    int ck = 0;
    for (int i = lane; i < tot; i += 32) ck += (H[i].w <= r2) ? 1 : 0;
    return __reduce_add_sync(0xffffffffu, ck);
}

__global__ void __launch_bounds__(128)
uniform_kernel(ULevels L) {
    const int g    = blockIdx.x;
    const int b    = g / NPOINT;
    const int gi   = g - b * NPOINT;
    const int tid  = threadIdx.x;
    const int w    = tid >> 5;
    const int lane = tid & 31;
    const float4* P4 = g_pcd4 + b * NPTS;

    // wait until fps has produced this center (release/acquire pipeline)
    if (tid == 0) {
        cuda::atomic_ref<int, cuda::thread_scope_device> pr(g_progress[b]);
        while (pr.load(cuda::memory_order_acquire) <= gi) __nanosleep(100);
    }
    __syncthreads();

    const float qx = g_newxyz[g*3], qy = g_newxyz[g*3+1], qz = g_newxyz[g*3+2];
    const float r2max = L.r2[4];

    __shared__ float4 Hseg[4*SEG];
    __shared__ float4 H[CAP];
    __shared__ int    s_cnt[4];

    int cnt = 0;
    const int start = w * (NPTS/4);
    for (int it = 0; it < (NPTS/4)/64; it++) {      // unroll x2: 2 pts in flight
        int j0 = start + it*64 + lane;
        int j1 = j0 + 32;
        float4 f0 = P4[j0];
        float4 f1 = P4[j1];
        float d0 = sqdist_f(f0.x, f0.y, f0.z, qx, qy, qz);
        float d1 = sqdist_f(f1.x, f1.y, f1.z, qx, qy, qz);
        bool h0 = (d0 <= r2max);
        unsigned m0 = __ballot_sync(0xffffffffu, h0);
        if (m0) {
            if (h0) {
                int pos = cnt + __popc(m0 & ((1u << lane) - 1u));
                if (pos < SEG) Hseg[w*SEG + pos] = make_float4(f0.x, f0.y, f0.z, d0);
            }
            cnt += __popc(m0);
        }
        bool h1 = (d1 <= r2max);
        unsigned m1 = __ballot_sync(0xffffffffu, h1);
        if (m1) {
            if (h1) {
                int pos = cnt + __popc(m1 & ((1u << lane) - 1u));
                if (pos < SEG) Hseg[w*SEG + pos] = make_float4(f1.x, f1.y, f1.z, d1);
            }
            cnt += __popc(m1);
        }
    }
    if (lane == 0) s_cnt[w] = cnt;
    __syncthreads();

    int c0 = s_cnt[0], c1 = s_cnt[1], c2 = s_cnt[2], c3 = s_cnt[3];
    bool ovf = (c0 > SEG) | (c1 > SEG) | (c2 > SEG) | (c3 > SEG);
    int tot = c0 + c1 + c2 + c3;

    if (!ovf) {
        int base = (w > 0 ? c0 : 0) + (w > 1 ? c1 : 0) + (w > 2 ? c2 : 0);
        int mycnt = s_cnt[w];
        for (int i = lane; i < mycnt; i += 32) H[base + i] = Hseg[w*SEG + i];
        __syncthreads();
        // per-warp level eval: w0->{0,1}, w1->{2}, w2->{3}, w3->{4}
        double acc = 0.0;
        if (w == 0) {
            #pragma unroll
            for (int k = 0; k < 2; k++) {
                int ck = count_hits(H, tot, L.r2[k], lane);
                float lsum = eval_level(H, tot, ck, L.r2[k], L.el[k], L.den[k],
                                        L.ns[k], lane);
                acc += L.w[k] * (double)lsum;
            }
        } else {
            int k = w + 1;                        // 2,3,4
            int ck = count_hits(H, tot, L.r2[k], lane);
            float lsum = eval_level(H, tot, ck, L.r2[k], L.el[k], L.den[k],
                                    L.ns[k], lane);
            acc += L.w[k] * (double)lsum;
        }
        #pragma unroll
        for (int o = 16; o > 0; o >>= 1)
            acc += __shfl_down_sync(0xffffffffu, acc, o);
        if (lane == 0 && acc != 0.0) atomicAdd(&g_acc[0], acc);
    } else {
        if (w == 0) {
            double acc = 0.0;
            for (int k = 0; k < 5; k++) {
                float r2 = L.r2[k];
                int ns = L.ns[k];
                int c = 0;
                for (int it = 0; it < NPTS/32; it++) {
                    int j = it*32 + lane;
                    float4 f = P4[j];
                    float d = sqdist_f(f.x, f.y, f.z, qx, qy, qz);
                    bool hit = (d <= r2);
                    unsigned m = __ballot_sync(0xffffffffu, hit);
                    if (hit) {
                        int pos = c + __popc(m & ((1u << lane) - 1u));
                        if (pos < ns) H[pos] = make_float4(f.x, f.y, f.z, d);
                    }
                    c += __popc(m);
                }
                int stored = c < ns ? c : ns;
                float lsum = eval_level(H, stored, c, r2, L.el[k], L.den[k], ns, lane);
                acc += L.w[k] * (double)lsum;
            }
            #pragma unroll
            for (int o = 16; o > 0; o >>= 1)
                acc += __shfl_down_sync(0xffffffffu, acc, o);
            if (lane == 0) atomicAdd(&g_acc[0], acc);
        }
    }
}

__global__ void finalize_kernel(float* out) {
    out[0] = (float)g_acc[0];
    out[1] = (float)(g_acc[1] / (double)(NB * NPTS * 4));
}

// ============================  launch  ============================
#define FPS_SMEM (NPTS * sizeof(float4))   /* 128 KB */

static cudaStream_t g_s2;
static cudaEvent_t  g_ev0, g_ev1;
struct _StreamInit {
    _StreamInit() {
        cudaStreamCreateWithFlags(&g_s2, cudaStreamNonBlocking);
        cudaEventCreateWithFlags(&g_ev0, cudaEventDisableTiming);
        cudaEventCreateWithFlags(&g_ev1, cudaEventDisableTiming);
        cudaFuncSetAttribute(fps_kernel,
                             cudaFuncAttributeMaxDynamicSharedMemorySize,
                             (int)FPS_SMEM);
    }
};
static _StreamInit g_stream_init;

extern "C" void kernel_launch(void* const* d_in, const int* in_sizes, int n_in,
                              void* d_out, int out_size) {
    const float* pcd = (const float*)d_in[0];
    float* out = (float*)d_out;

    // stream0: sort -> fps;  s2: repulsion -> uniform (uniform pipelines on fps
    // progress via acquire-spin; dispatched after repulsion so fps is already
    // resident — no placement deadlock possible).
    sort_kernel<<<NB, 1024>>>(pcd);              // zeroes g_acc + g_progress

    cudaEventRecord(g_ev0, 0);
    cudaStreamWaitEvent(g_s2, g_ev0, 0);
    {
        float r2     = (float)(0.07 * 0.07);
        float radius = (float)0.07;
        float hh     = (float)(0.03 * 0.03);
        repulsion_kernel<<<NB * (NPTS / RTILE), RTILE, 0, g_s2>>>(pcd, r2, radius, hh);
    }

    fps_kernel<<<NB, 512, FPS_SMEM>>>(pcd);

    {
        static const double PS[5] = {0.004, 0.008, 0.01, 0.012, 0.016};
        ULevels L;
        for (int k = 0; k < 5; k++) {
            double p  = PS[k];
            int    ns = (int)(8192.0 * p);
            double r  = sqrt(p * 1.0);
            double disk = M_PI * 1.0 * p / (double)ns;
            double el   = sqrt(2.0 * disk / 1.732);
            L.r2[k]  = (float)(r * r);
            L.el[k]  = (float)el;
            L.den[k] = (float)(el + 1e-8);
            L.w[k]   = (p * 100.0) * (p * 100.0) / ((double)NG * (double)ns) / 5.0;
            L.ns[k]  = ns;
        }
        uniform_kernel<<<NG, 128, 0, g_s2>>>(L);   // after repulsion on s2
    }
    cudaEventRecord(g_ev1, g_s2);

    cudaStreamWaitEvent(0, g_ev1, 0);
    finalize_kernel<<<1, 1>>>(out);
}

// round 14
// speedup vs baseline: 1.1079x; 1.1079x over previous
#include <cuda_runtime.h>
#include <cuda/atomic>
#include <math.h>

#define NB     4
#define NPTS   8192
#define NPOINT 409          /* int(8192*0.05) */
#define NG     (NB*NPOINT)  /* 1636 */
#define CAP    256
#define SEG    32           /* per-1024-pt-segment hit cap; 8*SEG == CAP */
#define NBKT   2048         /* counting-sort buckets (11-bit Morton prefix) */
#define RTILE  256
#define NBLK_REP (NB*(NPTS/RTILE))   /* 128 */
#define TOTAL_BLKS (NG + NBLK_REP)   /* 1764 */

// ---------------- device scratch (no allocations allowed) ----------------
__device__ double g_acc[2];                   // [0]=uniform, [1]=repulsion sum
__device__ float  g_newxyz[NB*NPOINT*3];      // FPS centers
__device__ float4 g_sorted[NB*NPTS];          // Morton-bucketed points (w = orig idx)
__device__ float4 g_pcd4[NB*NPTS];            // original-order points, float4
__device__ unsigned g_done;                   // completion counter

// exact-rounding distance (FPS argmax must match reference exactly)
__device__ __forceinline__ float sqdist_rn(float ax, float ay, float az,
                                           float bx, float by, float bz) {
    float dx = __fadd_rn(ax, -bx);
    float dy = __fadd_rn(ay, -by);
    float dz = __fadd_rn(az, -bz);
    return __fadd_rn(__fadd_rn(__fmul_rn(dx, dx), __fmul_rn(dy, dy)),
                     __fmul_rn(dz, dz));
}
// fast distance (FMA) — continuous-use sites only
__device__ __forceinline__ float sqdist_f(float ax, float ay, float az,
                                          float bx, float by, float bz) {
    float dx = ax - bx, dy = ay - by, dz = az - bz;
    return fmaf(dx, dx, fmaf(dy, dy, dz * dz));
}

__device__ __forceinline__ float warp_sum(float v) {
    #pragma unroll
    for (int o = 16; o > 0; o >>= 1) v += __shfl_down_sync(0xffffffffu, v, o);
    return v;
}

// last-block-out: after this block's g_acc contributions are complete
__device__ __forceinline__ void block_done(float* out) {
    __threadfence();
    cuda::atomic_ref<unsigned, cuda::thread_scope_device> dn(g_done);
    if (dn.fetch_add(1, cuda::memory_order_acq_rel) == TOTAL_BLKS - 1) {
        out[0] = (float)g_acc[0];
        out[1] = (float)(g_acc[1] / (double)(NB * NPTS * 4));
    }
}

// ============  Morton counting sort (2048 buckets): one block/batch  ============
__device__ __forceinline__ unsigned expandb(unsigned v) {
    v &= 1023u;
    v = (v | (v << 16)) & 0x030000FFu;
    v = (v | (v << 8))  & 0x0300F00Fu;
    v = (v | (v << 4))  & 0x030C30C3u;
    v = (v | (v << 2))  & 0x09249249u;
    return v;
}

__global__ void __launch_bounds__(1024, 1)
sort_kernel(const float* __restrict__ pcd) {
    __shared__ unsigned codes[NPTS];              // 32 KB: (bucket<<13)|orig_idx
    __shared__ int hist[NBKT];                    // 8 KB
    __shared__ int wsum[32];
    const int b    = blockIdx.x;
    const int tid  = threadIdx.x;
    const int lane = tid & 31;
    const int w    = tid >> 5;
    const float* P = pcd + b * NPTS * 3;

    if (b == 0 && tid == 0) { g_acc[0] = 0.0; g_acc[1] = 0.0; g_done = 0u; }

    for (int i = tid; i < NBKT; i += 1024) hist[i] = 0;
    __syncthreads();

    for (int j = tid; j < NPTS; j += 1024) {
        float x = P[3*j], y = P[3*j+1], z = P[3*j+2];
        g_pcd4[b*NPTS + j] = make_float4(x, y, z, 0.0f);
        unsigned ux = (unsigned)fminf(fmaxf((x + 1.0f) * 32.0f, 0.0f), 63.0f);
        unsigned uy = (unsigned)fminf(fmaxf((y + 1.0f) * 32.0f, 0.0f), 63.0f);
        unsigned uz = (unsigned)fminf(fmaxf((z + 1.0f) * 32.0f, 0.0f), 63.0f);
        unsigned m = expandb(ux) | (expandb(uy) << 1) | (expandb(uz) << 2); // 18 bits
        unsigned bkt = m >> 7;                    // 11-bit bucket
        codes[j] = (bkt << 13) | (unsigned)j;
        atomicAdd(&hist[bkt], 1);
    }
    __syncthreads();

    // exclusive prefix over 2048 buckets (2 per thread)
    int base = tid * 2;
    int s0 = hist[base], s1 = hist[base+1];
    int tsum = s0 + s1;
    int scan = tsum;
    #pragma unroll
    for (int o = 1; o < 32; o <<= 1) {
        int v = __shfl_up_sync(0xffffffffu, scan, o);
        if (lane >= o) scan += v;
    }
    if (lane == 31) wsum[w] = scan;
    __syncthreads();
    if (w == 0) {
        int v = wsum[lane], s = v;
        #pragma unroll
        for (int o = 1; o < 32; o <<= 1) {
            int t = __shfl_up_sync(0xffffffffu, s, o);
            if (lane >= o) s += t;
        }
        wsum[lane] = s - v;                       // exclusive warp offsets
    }
    __syncthreads();
    int excl = wsum[w] + (scan - tsum);
    hist[base]   = excl;
    hist[base+1] = excl + s0;
    __syncthreads();

    // scatter (order within bucket arbitrary — only grouping matters)
    for (int j = tid; j < NPTS; j += 1024) {
        unsigned c = codes[j];
        int bkt = (int)(c >> 13);
        int src = (int)(c & 0x1FFFu);
        int pos = atomicAdd(&hist[bkt], 1);
        float4 f = g_pcd4[b*NPTS + src];
        f.w = __int_as_float(src);
        g_sorted[b*NPTS + pos] = f;
    }
}

// ======  FPS: 512 thr, 2×8-pt AABB groups/lane, cached warp keys, redux  ======
__global__ void __launch_bounds__(512, 1)
fps_kernel(const float* __restrict__ pcd) {
    extern __shared__ float4 ctab[];              // [NPTS] orig-index coords, 128 KB

    const int b    = blockIdx.x;
    const int tid  = threadIdx.x;
    const int w    = tid >> 5;                    // 0..15
    const int lane = tid & 31;
    const float4* S  = g_sorted + b * NPTS;
    const float4* P4 = g_pcd4  + b * NPTS;
    const float*  P  = pcd + b * NPTS * 3;

    for (int j = tid; j < NPTS; j += 512)
        ctab[j] = P4[j];

    // lane owns 16 CONTIGUOUS bucketed points [tid*16, tid*16+16) as 2 groups of 8
    float xs[16], ys[16], zs[16], dist[16];
    unsigned loid[16];                            // 8191 - orig_idx
    #pragma unroll
    for (int k = 0; k < 16; k++) {
        float4 f = S[tid*16 + k];
        xs[k] = f.x; ys[k] = f.y; zs[k] = f.z;
        dist[k] = 1e10f;
        loid[k] = 8191u - (unsigned)__float_as_int(f.w);
    }

    // per-group AABBs
    float lox0=xs[0],hix0=xs[0],loy0=ys[0],hiy0=ys[0],loz0=zs[0],hiz0=zs[0];
    float lox1=xs[8],hix1=xs[8],loy1=ys[8],hiy1=ys[8],loz1=zs[8],hiz1=zs[8];
    #pragma unroll
    for (int k = 1; k < 8; k++) {
        lox0=fminf(lox0,xs[k]);   hix0=fmaxf(hix0,xs[k]);
        loy0=fminf(loy0,ys[k]);   hiy0=fmaxf(hiy0,ys[k]);
        loz0=fminf(loz0,zs[k]);   hiz0=fmaxf(hiz0,zs[k]);
        lox1=fminf(lox1,xs[8+k]); hix1=fmaxf(hix1,xs[8+k]);
        loy1=fminf(loy1,ys[8+k]); hiy1=fmaxf(hiy1,ys[8+k]);
        loz1=fminf(loz1,zs[8+k]); hiz1=fmaxf(hiz1,zs[8+k]);
    }

    // per-group cached keys (max dist | tie-break) and lane key
    unsigned long long gkey0, gkey1, lkey;
    {
        unsigned b0 = 0, b1 = 0;
        #pragma unroll
        for (int k = 0; k < 8; k++) {
            b0 = loid[k]   > b0 ? loid[k]   : b0;
            b1 = loid[8+k] > b1 ? loid[8+k] : b1;
        }
        unsigned long long hi = (unsigned long long)__float_as_uint(1e10f) << 32;
        gkey0 = hi | b0; gkey1 = hi | b1;
        lkey  = gkey0 > gkey1 ? gkey0 : gkey1;
    }
    float dmax0 = 1e10f, dmax1 = 1e10f;

    __shared__ unsigned long long skey[32];
    if (tid < 32) skey[tid] = 0ull;               // lanes 16..31 stay 0 (never win)

    float fx = P[0], fy = P[1], fz = P[2];        // far_0 = original index 0
    if (tid == 0) {
        g_newxyz[b*NPOINT*3 + 0] = fx;
        g_newxyz[b*NPOINT*3 + 1] = fy;
        g_newxyz[b*NPOINT*3 + 2] = fz;
    }
    __syncthreads();

    for (int s = 1; s < NPOINT; s++) {
        // per-group lower bounds (deflated for fp safety)
        float ax0 = fmaxf(fmaxf(lox0 - fx, fx - hix0), 0.0f);
        float ay0 = fmaxf(fmaxf(loy0 - fy, fy - hiy0), 0.0f);
        float az0 = fmaxf(fmaxf(loz0 - fz, fz - hiz0), 0.0f);
        bool a0 = (ax0*ax0 + ay0*ay0 + az0*az0) * 0.999f < dmax0;
        float ax1 = fmaxf(fmaxf(lox1 - fx, fx - hix1), 0.0f);
        float ay1 = fmaxf(fmaxf(loy1 - fy, fy - hiy1), 0.0f);
        float az1 = fmaxf(fmaxf(loz1 - fz, fz - hiz1), 0.0f);
        bool a1 = (ax1*ax1 + ay1*ay1 + az1*az1) * 0.999f < dmax1;

        if (__ballot_sync(0xffffffffu, a0 | a1)) {
            if (a0) {
                unsigned long long kmax = 0ull;
                #pragma unroll
                for (int k = 0; k < 8; k++) {
                    float d  = sqdist_rn(xs[k], ys[k], zs[k], fx, fy, fz);
                    float nd = fminf(dist[k], d);
                    dist[k]  = nd;
                    unsigned long long kk =
                        ((unsigned long long)__float_as_uint(nd) << 32) | loid[k];
                    kmax = kk > kmax ? kk : kmax;
                }
                gkey0 = kmax;
                dmax0 = __uint_as_float((unsigned)(kmax >> 32));
            }
            if (a1) {
                unsigned long long kmax = 0ull;
                #pragma unroll
                for (int k = 0; k < 8; k++) {
                    float d  = sqdist_rn(xs[8+k], ys[8+k], zs[8+k], fx, fy, fz);
                    float nd = fminf(dist[8+k], d);
                    dist[8+k] = nd;
                    unsigned long long kk =
                        ((unsigned long long)__float_as_uint(nd) << 32) | loid[8+k];
                    kmax = kk > kmax ? kk : kmax;
                }
                gkey1 = kmax;
                dmax1 = __uint_as_float((unsigned)(kmax >> 32));
            }
            if (a0 | a1) lkey = gkey0 > gkey1 ? gkey0 : gkey1;
            // warp argmax (only when warp has an active lane; else skey stale-valid)
            unsigned vb = (unsigned)(lkey >> 32);
            unsigned m  = __reduce_max_sync(0xffffffffu, vb);
            unsigned lo = (vb == m) ? (unsigned)lkey : 0u;
            unsigned l  = __reduce_max_sync(0xffffffffu, lo);
            if (lane == 0)
                skey[w] = ((unsigned long long)m << 32) | l;
        }
        __syncthreads();
        // every warp redundantly reduces the 16 warp keys (no 2nd barrier)
        unsigned long long k = skey[lane];
        unsigned hi2 = (unsigned)(k >> 32);
        unsigned m2  = __reduce_max_sync(0xffffffffu, hi2);
        unsigned lo2 = (hi2 == m2) ? (unsigned)k : 0u;
        unsigned l2  = __reduce_max_sync(0xffffffffu, lo2);
        int oi = 8191 - (int)l2;
        float4 c = ctab[oi];                      // same addr warp-wide: broadcast
        fx = c.x; fy = c.y; fz = c.z;
        if (tid == 0) {
            g_newxyz[(b*NPOINT + s)*3 + 0] = fx;
            g_newxyz[(b*NPOINT + s)*3 + 1] = fy;
            g_newxyz[(b*NPOINT + s)*3 + 2] = fz;
        }
    }
}

// =====================  Repulsion: one thread per query point  =====================
#define INSERT5(dv) do {                                   \
    float _d = (dv);                                       \
    if (_d < s4) { s4 = _d;                                \
        if (s4 < s3) { float _t = s3; s3 = s4; s4 = _t; }  \
        if (s3 < s2) { float _t = s2; s2 = s3; s3 = _t; }  \
        if (s2 < s1) { float _t = s1; s1 = s2; s2 = _t; }  \
        if (s1 < s0) { float _t = s0; s0 = s1; s1 = _t; }  \
    } } while (0)

__global__ void __launch_bounds__(RTILE)
repulsion_kernel(const float* __restrict__ pcd, float r2, float radius, float hh,
                 float* out) {
    const int blocks_per_b = NPTS / RTILE;
    const int b  = blockIdx.x / blocks_per_b;
    const int qi = (blockIdx.x % blocks_per_b) * RTILE + threadIdx.x;
    const float* P = pcd + b * NPTS * 3;

    const float qx = P[3*qi], qy = P[3*qi+1], qz = P[3*qi+2];

    __shared__ float4 sp[RTILE];

    float s0 = 1e30f, s1 = 1e30f, s2 = 1e30f, s3 = 1e30f, s4 = 1e30f;
    int   c  = 0;
    float h0 = 0.0f;

    for (int t = 0; t < NPTS; t += RTILE) {
        int j = t + threadIdx.x;
        sp[threadIdx.x] = make_float4(P[3*j], P[3*j+1], P[3*j+2], 0.0f);
        __syncthreads();
        #pragma unroll 8
        for (int u = 0; u < RTILE; u++) {
            float4 p = sp[u];
            float d = sqdist_f(p.x, p.y, p.z, qx, qy, qz);
            if (d <= r2 && c < 20) {
                if (c == 0) h0 = d;
                c++;
                INSERT5(d);
            }
        }
        __syncthreads();
    }

    int pads = 20 - c;
    if (pads > 5) pads = 5;
    for (int k = 0; k < pads; k++) INSERT5(h0);

    float acc = 0.0f;
    acc += radius - sqrtf(s1) * expf(-(s1 / hh));
    acc += radius - sqrtf(s2) * expf(-(s2 / hh));
    acc += radius - sqrtf(s3) * expf(-(s3 / hh));
    acc += radius - sqrtf(s4) * expf(-(s4 / hh));

    float ws = warp_sum(acc);
    __shared__ float red[RTILE/32];
    if ((threadIdx.x & 31) == 0) red[threadIdx.x >> 5] = ws;
    __syncthreads();
    if (threadIdx.x == 0) {
        float tot = 0.0f;
        #pragma unroll
        for (int w = 0; w < RTILE/32; w++) tot += red[w];
        atomicAdd(&g_acc[1], (double)tot);
        block_done(out);
    }
}

// ======  Uniform loss: one BLOCK per center, 8-warp scan, 4-warp eval  ======
struct ULevels {
    float  r2[5];
    float  el[5];
    float  den[5];
    double w[5];
    int    ns[5];
};

__device__ float eval_level(const float4* H, int n_stored, int true_cnt,
                            float r2, float el, float den, int ns, int lane)
{
    int u = true_cnt < ns ? true_cnt : ns;
    float lsum = 0.0f;
    int jstart = 0;
    if (u < ns) {
        if (lane == 0) {
            float ud = sqrtf(1e-8f);
            float t  = ud - el;
            lsum += (float)(ns - u + 1) * ((t * t) / den);
        }
        jstart = 1;
    }
    for (int j = jstart + lane; j < u; j += 32) {
        float xj = 0.f, yj = 0.f, zj = 0.f;
        int seen = 0;
        for (int i = 0; i < n_stored; i++) {
            float4 h = H[i];
            if (h.w <= r2) {
                if (seen == j) { xj = h.x; yj = h.y; zj = h.z; break; }
                seen++;
            }
        }
        float m1 = 1e30f;
        seen = 0;
        for (int i = 0; i < n_stored && seen < u; i++) {
            float4 h = H[i];
            if (h.w <= r2) {
                if (seen != j) {
                    float d = sqdist_f(h.x, h.y, h.z, xj, yj, zj);
                    m1 = fminf(m1, d);
                }
                seen++;
            }
        }
        float ud = sqrtf(fabsf(m1 + 1e-8f));
        float t  = ud - el;
        lsum += (t * t) / den;
    }
    return lsum;
}

// warp-parallel count of hits at radius r2 among H[0..tot)
__device__ __forceinline__ int count_hits(const float4* H, int tot, float r2, int lane) {
    int ck = 0;
    for (int i = lane; i < tot; i += 32) ck += (H[i].w <= r2) ? 1 : 0;
    return __reduce_add_sync(0xffffffffu, ck);
}

__global__ void __launch_bounds__(256)
uniform_kernel(ULevels L, float* out) {
    const int g    = blockIdx.x;
    const int b    = g / NPOINT;
    const int tid  = threadIdx.x;
    const int w    = tid >> 5;                    // 0..7
    const int lane = tid & 31;
    const float4* P4 = g_pcd4 + b * NPTS;

    const float qx = g_newxyz[g*3], qy = g_newxyz[g*3+1], qz = g_newxyz[g*3+2];
    const float r2max = L.r2[4];

    __shared__ float4 Hseg[8*SEG];                // 4 KB
    __shared__ float4 H[CAP];                     // 4 KB
    __shared__ int    s_cnt[8];

    int cnt = 0;
    const int start = w * (NPTS/8);               // 1024-pt segment per warp
    for (int it = 0; it < (NPTS/8)/64; it++) {    // 16 iters, 2 pts in flight
        int j0 = start + it*64 + lane;
        int j1 = j0 + 32;
        float4 f0 = P4[j0];
        float4 f1 = P4[j1];
        float d0 = sqdist_f(f0.x, f0.y, f0.z, qx, qy, qz);
        float d1 = sqdist_f(f1.x, f1.y, f1.z, qx, qy, qz);
        bool h0 = (d0 <= r2max);
        unsigned m0 = __ballot_sync(0xffffffffu, h0);
        if (m0) {
            if (h0) {
                int pos = cnt + __popc(m0 & ((1u << lane) - 1u));
                if (pos < SEG) Hseg[w*SEG + pos] = make_float4(f0.x, f0.y, f0.z, d0);
            }
            cnt += __popc(m0);
        }
        bool h1 = (d1 <= r2max);
        unsigned m1 = __ballot_sync(0xffffffffu, h1);
        if (m1) {
            if (h1) {
                int pos = cnt + __popc(m1 & ((1u << lane) - 1u));
                if (pos < SEG) Hseg[w*SEG + pos] = make_float4(f1.x, f1.y, f1.z, d1);
            }
            cnt += __popc(m1);
        }
    }
    if (lane == 0) s_cnt[w] = cnt;
    __syncthreads();

    bool ovf = false;
    int tot = 0;
    int base = 0;
    #pragma unroll
    for (int i = 0; i < 8; i++) {
        int ci = s_cnt[i];
        ovf |= (ci > SEG);
        if (i < w) base += ci;
        tot += ci;
    }

    if (!ovf) {
        int mycnt = s_cnt[w];
        for (int i = lane; i < mycnt; i += 32) H[base + i] = Hseg[w*SEG + i];
        __syncthreads();
        // per-warp level eval: w0->{0,1}, w1->{2}, w2->{3}, w3->{4}; w4..7 idle
        double acc = 0.0;
        if (w == 0) {
            #pragma unroll
            for (int k = 0; k < 2; k++) {
                int ck = count_hits(H, tot, L.r2[k], lane);
                float lsum = eval_level(H, tot, ck, L.r2[k], L.el[k], L.den[k],
                                        L.ns[k], lane);
                acc += L.w[k] * (double)lsum;
            }
        } else if (w < 4) {
            int k = w + 1;                        // 2,3,4
            int ck = count_hits(H, tot, L.r2[k], lane);
            float lsum = eval_level(H, tot, ck, L.r2[k], L.el[k], L.den[k],
                                    L.ns[k], lane);
            acc += L.w[k] * (double)lsum;
        }
        #pragma unroll
        for (int o = 16; o > 0; o >>= 1)
            acc += __shfl_down_sync(0xffffffffu, acc, o);
        if (lane == 0 && acc != 0.0) atomicAdd(&g_acc[0], acc);
    } else {
        if (w == 0) {
            double acc = 0.0;
            for (int k = 0; k < 5; k++) {
                float r2 = L.r2[k];
                int ns = L.ns[k];
                int c = 0;
                for (int it = 0; it < NPTS/32; it++) {
                    int j = it*32 + lane;
                    float4 f = P4[j];
                    float d = sqdist_f(f.x, f.y, f.z, qx, qy, qz);
                    bool hit = (d <= r2);
                    unsigned m = __ballot_sync(0xffffffffu, hit);
                    if (hit) {
                        int pos = c + __popc(m & ((1u << lane) - 1u));
                        if (pos < ns) H[pos] = make_float4(f.x, f.y, f.z, d);
                    }
                    c += __popc(m);
                }
                int stored = c < ns ? c : ns;
                float lsum = eval_level(H, stored, c, r2, L.el[k], L.den[k], ns, lane);
                acc += L.w[k] * (double)lsum;
            }
            #pragma unroll
            for (int o = 16; o > 0; o >>= 1)
                acc += __shfl_down_sync(0xffffffffu, acc, o);
            if (lane == 0) atomicAdd(&g_acc[0], acc);
        }
    }

    __syncthreads();
    if (tid == 0) block_done(out);
}

// ============================  launch  ============================
#define FPS_SMEM (NPTS * sizeof(float4))   /* 128 KB */

static cudaStream_t g_s2;
static cudaEvent_t  g_ev0, g_ev1;
struct _StreamInit {
    _StreamInit() {
        cudaStreamCreateWithFlags(&g_s2, cudaStreamNonBlocking);
        cudaEventCreateWithFlags(&g_ev0, cudaEventDisableTiming);
        cudaEventCreateWithFlags(&g_ev1, cudaEventDisableTiming);
        cudaFuncSetAttribute(fps_kernel,
                             cudaFuncAttributeMaxDynamicSharedMemorySize,
                             (int)FPS_SMEM);
    }
};
static _StreamInit g_stream_init;

extern "C" void kernel_launch(void* const* d_in, const int* in_sizes, int n_in,
                              void* d_out, int out_size) {
    const float* pcd = (const float*)d_in[0];
    float* out = (float*)d_out;

    // R12 ordering (measured best): sort alone; fork repulsion; fps; uniform.
    sort_kernel<<<NB, 1024>>>(pcd);              // zeroes g_acc + g_done

    cudaEventRecord(g_ev0, 0);
    cudaStreamWaitEvent(g_s2, g_ev0, 0);
    {
        float r2     = (float)(0.07 * 0.07);
        float radius = (float)0.07;
        float hh     = (float)(0.03 * 0.03);
        repulsion_kernel<<<NBLK_REP, RTILE, 0, g_s2>>>(pcd, r2, radius, hh, out);
    }
    cudaEventRecord(g_ev1, g_s2);

    fps_kernel<<<NB, 512, FPS_SMEM>>>(pcd);

    {
        static const double PS[5] = {0.004, 0.008, 0.01, 0.012, 0.016};
        ULevels L;
        for (int k = 0; k < 5; k++) {
            double p  = PS[k];
            int    ns = (int)(8192.0 * p);
            double r  = sqrt(p * 1.0);
            double disk = M_PI * 1.0 * p / (double)ns;
            double el   = sqrt(2.0 * disk / 1.732);
            L.r2[k]  = (float)(r * r);
            L.el[k]  = (float)el;
            L.den[k] = (float)(el + 1e-8);
            L.w[k]   = (p * 100.0) * (p * 100.0) / ((double)NG * (double)ns) / 5.0;
            L.ns[k]  = ns;
        }
        uniform_kernel<<<NG, 256>>>(L, out);
    }

    // join s2 back into the origin stream (graph capture requires it); the
    // last-finishing block has already written `out` — no finalize kernel.
    cudaStreamWaitEvent(0, g_ev1, 0);
}

// round 15
// speedup vs baseline: 1.3290x; 1.1995x over previous
#include <cuda_runtime.h>
#include <cuda/atomic>
#include <math.h>

#define NB     4
#define NPTS   8192
#define NPOINT 409          /* int(8192*0.05) */
#define NG     (NB*NPOINT)  /* 1636 */
#define NBKT   2048         /* counting-sort buckets (11-bit Morton prefix) */
#define RBLK   256
#define NBLK_REP (NB*(NPTS/RBLK))    /* 128 */
#define TOTAL_BLKS (NG + NBLK_REP)   /* 1764 */

// ---------------- device scratch (no allocations allowed) ----------------
__device__ double g_acc[2];                   // [0]=uniform, [1]=repulsion sum
__device__ float  g_newxyz[NB*NPOINT*3];      // FPS centers
__device__ float4 g_sorted[NB*NPTS];          // Morton-bucketed points (w = orig idx)
__device__ float4 g_pcd4[NB*NPTS];            // original-order points, float4
__device__ int    g_bktoff[NB*(NBKT+1)];      // bucket start offsets + sentinel
__device__ unsigned g_done;                   // completion counter

// exact-rounding distance (FPS argmax must match reference exactly)
__device__ __forceinline__ float sqdist_rn(float ax, float ay, float az,
                                           float bx, float by, float bz) {
    float dx = __fadd_rn(ax, -bx);
    float dy = __fadd_rn(ay, -by);
    float dz = __fadd_rn(az, -bz);
    return __fadd_rn(__fadd_rn(__fmul_rn(dx, dx), __fmul_rn(dy, dy)),
                     __fmul_rn(dz, dz));
}
// fast distance (FMA) — continuous-use sites only
__device__ __forceinline__ float sqdist_f(float ax, float ay, float az,
                                          float bx, float by, float bz) {
    float dx = ax - bx, dy = ay - by, dz = az - bz;
    return fmaf(dx, dx, fmaf(dy, dy, dz * dz));
}

__device__ __forceinline__ float warp_sum(float v) {
    #pragma unroll
    for (int o = 16; o > 0; o >>= 1) v += __shfl_down_sync(0xffffffffu, v, o);
    return v;
}

// last-block-out: after this block's g_acc contributions are complete
__device__ __forceinline__ void block_done(float* out) {
    __threadfence();
    cuda::atomic_ref<unsigned, cuda::thread_scope_device> dn(g_done);
    if (dn.fetch_add(1, cuda::memory_order_acq_rel) == TOTAL_BLKS - 1) {
        out[0] = (float)g_acc[0];
        out[1] = (float)(g_acc[1] / (double)(NB * NPTS * 4));
    }
}

// ============  Morton helpers  ============
__device__ __forceinline__ unsigned expandb(unsigned v) {
    v &= 1023u;
    v = (v | (v << 16)) & 0x030000FFu;
    v = (v | (v << 8))  & 0x0300F00Fu;
    v = (v | (v << 4))  & 0x030C30C3u;
    v = (v | (v << 2))  & 0x09249249u;
    return v;
}
// bucket id of bucket coords (bx in [0,7], by,bz in [0,15])
__device__ __forceinline__ int bucket_of(int bx, int by, int bz) {
    unsigned m = expandb((unsigned)(bx << 3))
               | (expandb((unsigned)(by << 2)) << 1)
               | (expandb((unsigned)(bz << 2)) << 2);
    return (int)(m >> 7);
}
// conservative cell range [c0,c1] covering coord interval q±r (±1 cell margin)
__device__ __forceinline__ void cell_range(float q, float r, int& c0, int& c1) {
    int lo = (int)floorf((q - r + 1.0f) * 32.0f) - 1;
    int hi = (int)floorf((q + r + 1.0f) * 32.0f) + 1;
    c0 = lo < 0 ? 0 : (lo > 63 ? 63 : lo);
    c1 = hi < 0 ? 0 : (hi > 63 ? 63 : hi);
}

// ============  Morton counting sort (2048 buckets): one block/batch  ============
__global__ void __launch_bounds__(1024, 1)
sort_kernel(const float* __restrict__ pcd) {
    __shared__ unsigned codes[NPTS];              // 32 KB: (bucket<<13)|orig_idx
    __shared__ int hist[NBKT];                    // 8 KB
    __shared__ int wsum[32];
    const int b    = blockIdx.x;
    const int tid  = threadIdx.x;
    const int lane = tid & 31;
    const int w    = tid >> 5;
    const float* P = pcd + b * NPTS * 3;

    if (b == 0 && tid == 0) { g_acc[0] = 0.0; g_acc[1] = 0.0; g_done = 0u; }
    if (tid == 0) g_bktoff[b*(NBKT+1) + NBKT] = NPTS;   // sentinel

    for (int i = tid; i < NBKT; i += 1024) hist[i] = 0;
    __syncthreads();

    for (int j = tid; j < NPTS; j += 1024) {
        float x = P[3*j], y = P[3*j+1], z = P[3*j+2];
        g_pcd4[b*NPTS + j] = make_float4(x, y, z, 0.0f);
        unsigned ux = (unsigned)fminf(fmaxf((x + 1.0f) * 32.0f, 0.0f), 63.0f);
        unsigned uy = (unsigned)fminf(fmaxf((y + 1.0f) * 32.0f, 0.0f), 63.0f);
        unsigned uz = (unsigned)fminf(fmaxf((z + 1.0f) * 32.0f, 0.0f), 63.0f);
        unsigned m = expandb(ux) | (expandb(uy) << 1) | (expandb(uz) << 2); // 18 bits
        unsigned bkt = m >> 7;                    // 11-bit bucket
        codes[j] = (bkt << 13) | (unsigned)j;
        atomicAdd(&hist[bkt], 1);
    }
    __syncthreads();

    // exclusive prefix over 2048 buckets (2 per thread)
    int base = tid * 2;
    int s0 = hist[base], s1 = hist[base+1];
    int tsum = s0 + s1;
    int scan = tsum;
    #pragma unroll
    for (int o = 1; o < 32; o <<= 1) {
        int v = __shfl_up_sync(0xffffffffu, scan, o);
        if (lane >= o) scan += v;
    }
    if (lane == 31) wsum[w] = scan;
    __syncthreads();
    if (w == 0) {
        int v = wsum[lane], s = v;
        #pragma unroll
        for (int o = 1; o < 32; o <<= 1) {
            int t = __shfl_up_sync(0xffffffffu, s, o);
            if (lane >= o) s += t;
        }
        wsum[lane] = s - v;                       // exclusive warp offsets
    }
    __syncthreads();
    int excl = wsum[w] + (scan - tsum);
    hist[base]   = excl;
    hist[base+1] = excl + s0;
    g_bktoff[b*(NBKT+1) + base]     = excl;       // bucket start table
    g_bktoff[b*(NBKT+1) + base + 1] = excl + s0;
    __syncthreads();

    // scatter (order within bucket arbitrary — consumers are order-free)
    for (int j = tid; j < NPTS; j += 1024) {
        unsigned c = codes[j];
        int bkt = (int)(c >> 13);
        int src = (int)(c & 0x1FFFu);
        int pos = atomicAdd(&hist[bkt], 1);
        float4 f = g_pcd4[b*NPTS + src];
        f.w = __int_as_float(src);
        g_sorted[b*NPTS + pos] = f;
    }
}

// ======  FPS: 512 thr, 2×8-pt AABB groups/lane, cached warp keys, redux  ======
__global__ void __launch_bounds__(512, 1)
fps_kernel(const float* __restrict__ pcd) {
    extern __shared__ float4 ctab[];              // [NPTS] orig-index coords, 128 KB

    const int b    = blockIdx.x;
    const int tid  = threadIdx.x;
    const int w    = tid >> 5;                    // 0..15
    const int lane = tid & 31;
    const float4* S  = g_sorted + b * NPTS;
    const float4* P4 = g_pcd4  + b * NPTS;
    const float*  P  = pcd + b * NPTS * 3;

    for (int j = tid; j < NPTS; j += 512)
        ctab[j] = P4[j];

    // lane owns 16 CONTIGUOUS bucketed points [tid*16, tid*16+16) as 2 groups of 8
    float xs[16], ys[16], zs[16], dist[16];
    unsigned loid[16];                            // 8191 - orig_idx
    #pragma unroll
    for (int k = 0; k < 16; k++) {
        float4 f = S[tid*16 + k];
        xs[k] = f.x; ys[k] = f.y; zs[k] = f.z;
        dist[k] = 1e10f;
        loid[k] = 8191u - (unsigned)__float_as_int(f.w);
    }

    // per-group AABBs
    float lox0=xs[0],hix0=xs[0],loy0=ys[0],hiy0=ys[0],loz0=zs[0],hiz0=zs[0];
    float lox1=xs[8],hix1=xs[8],loy1=ys[8],hiy1=ys[8],loz1=zs[8],hiz1=zs[8];
    #pragma unroll
    for (int k = 1; k < 8; k++) {
        lox0=fminf(lox0,xs[k]);   hix0=fmaxf(hix0,xs[k]);
        loy0=fminf(loy0,ys[k]);   hiy0=fmaxf(hiy0,ys[k]);
        loz0=fminf(loz0,zs[k]);   hiz0=fmaxf(hiz0,zs[k]);
        lox1=fminf(lox1,xs[8+k]); hix1=fmaxf(hix1,xs[8+k]);
        loy1=fminf(loy1,ys[8+k]); hiy1=fmaxf(hiy1,ys[8+k]);
        loz1=fminf(loz1,zs[8+k]); hiz1=fmaxf(hiz1,zs[8+k]);
    }

    // per-group cached keys (max dist | tie-break) and lane key
    unsigned long long gkey0, gkey1, lkey;
    {
        unsigned b0 = 0, b1 = 0;
        #pragma unroll
        for (int k = 0; k < 8; k++) {
            b0 = loid[k]   > b0 ? loid[k]   : b0;
            b1 = loid[8+k] > b1 ? loid[8+k] : b1;
        }
        unsigned long long hi = (unsigned long long)__float_as_uint(1e10f) << 32;
        gkey0 = hi | b0; gkey1 = hi | b1;
        lkey  = gkey0 > gkey1 ? gkey0 : gkey1;
    }
    float dmax0 = 1e10f, dmax1 = 1e10f;

    __shared__ unsigned long long skey[32];
    if (tid < 32) skey[tid] = 0ull;               // lanes 16..31 stay 0 (never win)

    float fx = P[0], fy = P[1], fz = P[2];        // far_0 = original index 0
    if (tid == 0) {
        g_newxyz[b*NPOINT*3 + 0] = fx;
        g_newxyz[b*NPOINT*3 + 1] = fy;
        g_newxyz[b*NPOINT*3 + 2] = fz;
    }
    __syncthreads();

    for (int s = 1; s < NPOINT; s++) {
        // per-group lower bounds (deflated for fp safety)
        float ax0 = fmaxf(fmaxf(lox0 - fx, fx - hix0), 0.0f);
        float ay0 = fmaxf(fmaxf(loy0 - fy, fy - hiy0), 0.0f);
        float az0 = fmaxf(fmaxf(loz0 - fz, fz - hiz0), 0.0f);
        bool a0 = (ax0*ax0 + ay0*ay0 + az0*az0) * 0.999f < dmax0;
        float ax1 = fmaxf(fmaxf(lox1 - fx, fx - hix1), 0.0f);
        float ay1 = fmaxf(fmaxf(loy1 - fy, fy - hiy1), 0.0f);
        float az1 = fmaxf(fmaxf(loz1 - fz, fz - hiz1), 0.0f);
        bool a1 = (ax1*ax1 + ay1*ay1 + az1*az1) * 0.999f < dmax1;

        if (__ballot_sync(0xffffffffu, a0 | a1)) {
            if (a0) {
                unsigned long long kmax = 0ull;
                #pragma unroll
                for (int k = 0; k < 8; k++) {
                    float d  = sqdist_rn(xs[k], ys[k], zs[k], fx, fy, fz);
                    float nd = fminf(dist[k], d);
                    dist[k]  = nd;
                    unsigned long long kk =
                        ((unsigned long long)__float_as_uint(nd) << 32) | loid[k];
                    kmax = kk > kmax ? kk : kmax;
                }
                gkey0 = kmax;
                dmax0 = __uint_as_float((unsigned)(kmax >> 32));
            }
            if (a1) {
                unsigned long long kmax = 0ull;
                #pragma unroll
                for (int k = 0; k < 8; k++) {
                    float d  = sqdist_rn(xs[8+k], ys[8+k], zs[8+k], fx, fy, fz);
                    float nd = fminf(dist[8+k], d);
                    dist[8+k] = nd;
                    unsigned long long kk =
                        ((unsigned long long)__float_as_uint(nd) << 32) | loid[8+k];
                    kmax = kk > kmax ? kk : kmax;
                }
                gkey1 = kmax;
                dmax1 = __uint_as_float((unsigned)(kmax >> 32));
            }
            if (a0 | a1) lkey = gkey0 > gkey1 ? gkey0 : gkey1;
            // warp argmax (only when warp has an active lane; else skey stale-valid)
            unsigned vb = (unsigned)(lkey >> 32);
            unsigned m  = __reduce_max_sync(0xffffffffu, vb);
            unsigned lo = (vb == m) ? (unsigned)lkey : 0u;
            unsigned l  = __reduce_max_sync(0xffffffffu, lo);
            if (lane == 0)
                skey[w] = ((unsigned long long)m << 32) | l;
        }
        __syncthreads();
        // every warp redundantly reduces the 16 warp keys (no 2nd barrier)
        unsigned long long k = skey[lane];
        unsigned hi2 = (unsigned)(k >> 32);
        unsigned m2  = __reduce_max_sync(0xffffffffu, hi2);
        unsigned lo2 = (hi2 == m2) ? (unsigned)k : 0u;
        unsigned l2  = __reduce_max_sync(0xffffffffu, lo2);
        int oi = 8191 - (int)l2;
        float4 c = ctab[oi];                      // same addr warp-wide: broadcast
        fx = c.x; fy = c.y; fz = c.z;
        if (tid == 0) {
            g_newxyz[(b*NPOINT + s)*3 + 0] = fx;
            g_newxyz[(b*NPOINT + s)*3 + 1] = fy;
            g_newxyz[(b*NPOINT + s)*3 + 2] = fz;
        }
    }
}

// ============  Repulsion: one thread per query, bucket gather  ============
#define INSERT5(dv) do {                                   \
    float _d = (dv);                                       \
    if (_d < s4) { s4 = _d;                                \
        if (s4 < s3) { float _t = s3; s3 = s4; s4 = _t; }  \
        if (s3 < s2) { float _t = s2; s2 = s3; s3 = _t; }  \
        if (s2 < s1) { float _t = s1; s1 = s2; s2 = _t; }  \
        if (s1 < s0) { float _t = s0; s0 = s1; s1 = _t; }  \
    } } while (0)

__global__ void __launch_bounds__(RBLK)
repulsion_kernel(float r2, float radius, float hh, float* out) {
    const int blocks_per_b = NPTS / RBLK;         // 32
    const int b  = blockIdx.x / blocks_per_b;
    const int qi = (blockIdx.x % blocks_per_b) * RBLK + threadIdx.x;
    const float4* P4 = g_pcd4 + b * NPTS;
    const float4* S  = g_sorted + b * NPTS;
    const int*    BO = g_bktoff + b * (NBKT+1);

    float4 q = P4[qi];
    const float qx = q.x, qy = q.y, qz = q.z;

    float s0 = 1e30f, s1 = 1e30f, s2 = 1e30f, s3 = 1e30f, s4 = 1e30f;
    int   c = 0, minidx = 0x7fffffff;
    float h0 = 0.0f;

    int cx0, cx1, cy0, cy1, cz0, cz1;
    cell_range(qx, radius, cx0, cx1);
    cell_range(qy, radius, cy0, cy1);
    cell_range(qz, radius, cz0, cz1);
    int bx0 = cx0 >> 3, bx1 = cx1 >> 3;
    int by0 = cy0 >> 2, by1 = cy1 >> 2;
    int bz0 = cz0 >> 2, bz1 = cz1 >> 2;

    for (int bz = bz0; bz <= bz1; bz++)
        for (int by = by0; by <= by1; by++)
            for (int bx = bx0; bx <= bx1; bx++) {
                int id = bucket_of(bx, by, bz);
                int s = BO[id], e = BO[id+1];
                for (int j = s; j < e; j++) {
                    float4 f = S[j];
                    float d = sqdist_f(f.x, f.y, f.z, qx, qy, qz);
                    if (d <= r2) {
                        c++;
                        int oi = __float_as_int(f.w);
                        if (oi < minidx) { minidx = oi; h0 = d; }
                        INSERT5(d);
                    }
                }
            }

    if (c > 20) {
        // exact fallback (never expected): first-20-hits in index order
        s0 = s1 = s2 = s3 = s4 = 1e30f; c = 0; h0 = 0.0f;
        for (int j = 0; j < NPTS; j++) {
            float4 f = P4[j];
            float d = sqdist_f(f.x, f.y, f.z, qx, qy, qz);
            if (d <= r2 && c < 20) {
                if (c == 0) h0 = d;
                c++;
                INSERT5(d);
            }
        }
    }

    int pads = 20 - c;
    if (pads > 5) pads = 5;
    for (int k = 0; k < pads; k++) INSERT5(h0);

    float acc = 0.0f;
    acc += radius - sqrtf(s1) * expf(-(s1 / hh));
    acc += radius - sqrtf(s2) * expf(-(s2 / hh));
    acc += radius - sqrtf(s3) * expf(-(s3 / hh));
    acc += radius - sqrtf(s4) * expf(-(s4 / hh));

    float ws = warp_sum(acc);
    __shared__ float red[RBLK/32];
    if ((threadIdx.x & 31) == 0) red[threadIdx.x >> 5] = ws;
    __syncthreads();
    if (threadIdx.x == 0) {
        float tot = 0.0f;
        #pragma unroll
        for (int w = 0; w < RBLK/32; w++) tot += red[w];
        atomicAdd(&g_acc[1], (double)tot);
        block_done(out);
    }
}

// ======  Uniform loss: one BLOCK per center, bucket gather + lane-per-hit eval  ======
struct ULevels {
    float  r2[5];
    float  el[5];
    float  den[5];
    double w[5];
    int    ns[5];
    float  rmax;
};

// order-free padded-mode level eval (valid when hit count < ns strictly)
__device__ double eval_level_fast(float x, float y, float z, float d, unsigned idx,
                                  int cnt, float r2k, float el, float den, int ns,
                                  int lane, double wk)
{
    bool fk = (d <= r2k);
    unsigned bal = __ballot_sync(0xffffffffu, fk);
    int u = __popc(bal);
    unsigned fidx = __reduce_min_sync(0xffffffffu, fk ? idx : 0x7fffffffu);
    float m1 = 1e30f;
    for (int j = 0; j < cnt; j++) {
        float dj = __shfl_sync(0xffffffffu, d, j);
        float xj = __shfl_sync(0xffffffffu, x, j);
        float yj = __shfl_sync(0xffffffffu, y, j);
        float zj = __shfl_sync(0xffffffffu, z, j);
        if (dj <= r2k && j != lane)
            m1 = fminf(m1, sqdist_f(xj, yj, zj, x, y, z));
    }
    double acc = 0.0;
    if (lane == 0) {
        float t = sqrtf(1e-8f) - el;
        acc += wk * (double)((float)(ns - u + 1) * ((t * t) / den));
    }
    if (fk && idx != fidx) {
        float ud = sqrtf(fabsf(m1 + 1e-8f));
        float t  = ud - el;
        acc += wk * (double)((t * t) / den);
    }
    return acc;
}

// ordered eval for fallback path (index-ordered H, seen-counting)
__device__ float eval_level(const float4* H, int n_stored, int true_cnt,
                            float r2, float el, float den, int ns, int lane)
{
    int u = true_cnt < ns ? true_cnt : ns;
    float lsum = 0.0f;
    int jstart = 0;
    if (u < ns) {
        if (lane == 0) {
            float ud = sqrtf(1e-8f);
            float t  = ud - el;
            lsum += (float)(ns - u + 1) * ((t * t) / den);
        }
        jstart = 1;
    }
    for (int j = jstart + lane; j < u; j += 32) {
        float xj = 0.f, yj = 0.f, zj = 0.f;
        int seen = 0;
        for (int i = 0; i < n_stored; i++) {
            float4 h = H[i];
            if (h.w <= r2) {
                if (seen == j) { xj = h.x; yj = h.y; zj = h.z; break; }
                seen++;
            }
        }
        float m1 = 1e30f;
        seen = 0;
        for (int i = 0; i < n_stored && seen < u; i++) {
            float4 h = H[i];
            if (h.w <= r2) {
                if (seen != j) {
                    float d = sqdist_f(h.x, h.y, h.z, xj, yj, zj);
                    m1 = fminf(m1, d);
                }
                seen++;
            }
        }
        float ud = sqrtf(fabsf(m1 + 1e-8f));
        float t  = ud - el;
        lsum += (t * t) / den;
    }
    return lsum;
}

__global__ void __launch_bounds__(128)
uniform_kernel(ULevels L, float* out) {
    const int g    = blockIdx.x;
    const int b    = g / NPOINT;
    const int tid  = threadIdx.x;
    const int w    = tid >> 5;                    // 0..3
    const int lane = tid & 31;
    const float4* P4 = g_pcd4 + b * NPTS;
    const float4* S  = g_sorted + b * NPTS;
    const int*    BO = g_bktoff + b * (NBKT+1);

    const float qx = g_newxyz[g*3], qy = g_newxyz[g*3+1], qz = g_newxyz[g*3+2];
    const float r2max = L.r2[4];

    __shared__ float4 H[64];
    __shared__ int    hidx[64];
    __shared__ int    scnt;
    if (tid == 0) scnt = 0;
    __syncthreads();

    // warp 0: gather hits at largest radius from candidate buckets
    if (w == 0) {
        int cx0, cx1, cy0, cy1, cz0, cz1;
        cell_range(qx, L.rmax, cx0, cx1);
        cell_range(qy, L.rmax, cy0, cy1);
        cell_range(qz, L.rmax, cz0, cz1);
        int bx0 = cx0 >> 3, nx = (cx1 >> 3) - bx0 + 1;
        int by0 = cy0 >> 2, ny = (cy1 >> 2) - by0 + 1;
        int bz0 = cz0 >> 2, nz = (cz1 >> 2) - bz0 + 1;
        int nb = nx * ny * nz;                    // <= 48
        for (int t = lane; t < nb; t += 32) {
            int bx = bx0 + (t % nx);
            int rem = t / nx;
            int by = by0 + (rem % ny);
            int bz = bz0 + (rem / ny);
            int id = bucket_of(bx, by, bz);
            int s = BO[id], e = BO[id+1];
            for (int j = s; j < e; j++) {
                float4 f = S[j];
                float d = sqdist_f(f.x, f.y, f.z, qx, qy, qz);
                if (d <= r2max) {
                    int pos = atomicAdd(&scnt, 1);
                    if (pos < 64) {
                        H[pos] = make_float4(f.x, f.y, f.z, d);
                        hidx[pos] = __float_as_int(f.w);
                    }
                }
            }
        }
    }
    __syncthreads();
    int cnt = scnt;

    if (cnt <= 31) {
        // fast path: hit count < every ns -> strictly padded mode, order-free
        float x = 0.f, y = 0.f, z = 0.f, d = 1e30f;
        unsigned idx = 0x7fffffffu;
        if (lane < cnt) {
            float4 h = H[lane];
            x = h.x; y = h.y; z = h.z; d = h.w;
            idx = (unsigned)hidx[lane];
        }
        double acc = 0.0;
        if (w == 0) {
            acc += eval_level_fast(x, y, z, d, idx, cnt, L.r2[0], L.el[0],
                                   L.den[0], L.ns[0], lane, L.w[0]);
            acc += eval_level_fast(x, y, z, d, idx, cnt, L.r2[1], L.el[1],
                                   L.den[1], L.ns[1], lane, L.w[1]);
        } else {
            int k = w + 1;                        // 2,3,4
            acc += eval_level_fast(x, y, z, d, idx, cnt, L.r2[k], L.el[k],
                                   L.den[k], L.ns[k], lane, L.w[k]);
        }
        #pragma unroll
        for (int o = 16; o > 0; o >>= 1)
            acc += __shfl_down_sync(0xffffffffu, acc, o);
        if (lane == 0 && acc != 0.0) atomicAdd(&g_acc[0], acc);
    } else {
        // exact fallback (never expected): index-ordered full scan per level
        __shared__ float4 HF[256];
        if (w == 0) {
            double acc = 0.0;
            for (int k = 0; k < 5; k++) {
                float r2 = L.r2[k];
                int ns = L.ns[k];
                int c = 0;
                for (int it = 0; it < NPTS/32; it++) {
                    int j = it*32 + lane;
                    float4 f = P4[j];
                    float d = sqdist_f(f.x, f.y, f.z, qx, qy, qz);
                    bool hit = (d <= r2);
                    unsigned m = __ballot_sync(0xffffffffu, hit);
                    if (hit) {
                        int pos = c + __popc(m & ((1u << lane) - 1u));
                        if (pos < ns) HF[pos] = make_float4(f.x, f.y, f.z, d);
                    }
                    c += __popc(m);
                }
                int stored = c < ns ? c : ns;
                float lsum = eval_level(HF, stored, c, r2, L.el[k], L.den[k],
                                        ns, lane);
                acc += L.w[k] * (double)lsum;
            }
            #pragma unroll
            for (int o = 16; o > 0; o >>= 1)
                acc += __shfl_down_sync(0xffffffffu, acc, o);
            if (lane == 0) atomicAdd(&g_acc[0], acc);
        }
    }

    __syncthreads();
    if (tid == 0) block_done(out);
}

// ============================  launch  ============================
#define FPS_SMEM (NPTS * sizeof(float4))   /* 128 KB */

static cudaStream_t g_s2;
static cudaEvent_t  g_ev0, g_ev1;
struct _StreamInit {
    _StreamInit() {
        cudaStreamCreateWithFlags(&g_s2, cudaStreamNonBlocking);
        cudaEventCreateWithFlags(&g_ev0, cudaEventDisableTiming);
        cudaEventCreateWithFlags(&g_ev1, cudaEventDisableTiming);
        cudaFuncSetAttribute(fps_kernel,
                             cudaFuncAttributeMaxDynamicSharedMemorySize,
                             (int)FPS_SMEM);
    }
};
static _StreamInit g_stream_init;

extern "C" void kernel_launch(void* const* d_in, const int* in_sizes, int n_in,
                              void* d_out, int out_size) {
    const float* pcd = (const float*)d_in[0];
    float* out = (float*)d_out;

    // main: sort -> fps -> uniform.  s2: (after sort) bucketed repulsion (~13us,
    // finishes early in fps — contention overlap nearly eliminated).
    sort_kernel<<<NB, 1024>>>(pcd);              // zeroes g_acc/g_done, fills buckets

    cudaEventRecord(g_ev0, 0);
    cudaStreamWaitEvent(g_s2, g_ev0, 0);
    {
        float r2     = (float)(0.07 * 0.07);
        float radius = (float)0.07;
        float hh     = (float)(0.03 * 0.03);
        repulsion_kernel<<<NBLK_REP, RBLK, 0, g_s2>>>(r2, radius, hh, out);
    }
    cudaEventRecord(g_ev1, g_s2);

    fps_kernel<<<NB, 512, FPS_SMEM>>>(pcd);

    {
        static const double PS[5] = {0.004, 0.008, 0.01, 0.012, 0.016};
        ULevels L;
        for (int k = 0; k < 5; k++) {
            double p  = PS[k];
            int    ns = (int)(8192.0 * p);
            double r  = sqrt(p * 1.0);
            double disk = M_PI * 1.0 * p / (double)ns;
            double el   = sqrt(2.0 * disk / 1.732);
            L.r2[k]  = (float)(r * r);
            L.el[k]  = (float)el;
            L.den[k] = (float)(el + 1e-8);
            L.w[k]   = (p * 100.0) * (p * 100.0) / ((double)NG * (double)ns) / 5.0;
            L.ns[k]  = ns;
        }
        L.rmax = (float)sqrt(0.016);
        uniform_kernel<<<NG, 128>>>(L, out);
    }

    cudaStreamWaitEvent(0, g_ev1, 0);
}